// round 3
// baseline (speedup 1.0000x reference)
#include <cuda_runtime.h>

// SpatialTransformer: out = trilinear_sample(src, grid+flow) with border clamp.
// src:  [1,1,160,192,160] f32   d_in[0]
// flow: [1,3,160,192,160] f32   d_in[1]  (channel-planar: d,h,w displacement)
// grid: identity meshgrid       d_in[2]  (IGNORED - recomputed from indices)
// out:  [1,1,160,192,160] f32
//
// Math collapse: the reference's normalize -> flip -> unnormalize chain reduces to
//   ux = (w + flow[2]) * W/(W-1) - 0.5   (x -> W axis)
//   uy = (h + flow[1]) * H/(H-1) - 0.5
//   uz = (d + flow[0]) * D/(D-1) - 0.5
// then clamp to [0, S-1], trilinear with clamped +1 neighbor (border padding).

#define DD 160
#define HH 192
#define WW 160
#define NN (DD * HH * WW)

__global__ __launch_bounds__(256) void st_warp_kernel(
    const float* __restrict__ src,
    const float* __restrict__ flow,
    float* __restrict__ out)
{
    const int i4 = blockIdx.x * blockDim.x + threadIdx.x;
    if (i4 >= NN / 4) return;
    const int idx = i4 * 4;

    // decompose linear index (idx..idx+3 share same h,d since W%4==0)
    const int w = idx % WW;
    const int t = idx / WW;
    const int h = t % HH;
    const int d = t / HH;

    // coalesced vector loads of the three flow planes
    const float4 fd = __ldg((const float4*)(flow + idx));            // D-displacement
    const float4 fh = __ldg((const float4*)(flow + NN + idx));       // H-displacement
    const float4 fw = __ldg((const float4*)(flow + 2 * NN + idx));   // W-displacement

    const float sx = (float)WW / (float)(WW - 1);
    const float sy = (float)HH / (float)(HH - 1);
    const float sz = (float)DD / (float)(DD - 1);

    float fwv[4] = {fw.x, fw.y, fw.z, fw.w};
    float fhv[4] = {fh.x, fh.y, fh.z, fh.w};
    float fdv[4] = {fd.x, fd.y, fd.z, fd.w};
    float res[4];

#pragma unroll
    for (int k = 0; k < 4; k++) {
        float ux = ((float)(w + k) + fwv[k]) * sx - 0.5f;
        float uy = ((float)h + fhv[k]) * sy - 0.5f;
        float uz = ((float)d + fdv[k]) * sz - 0.5f;

        ux = fminf(fmaxf(ux, 0.0f), (float)(WW - 1));
        uy = fminf(fmaxf(uy, 0.0f), (float)(HH - 1));
        uz = fminf(fmaxf(uz, 0.0f), (float)(DD - 1));

        const float x0f = floorf(ux);
        const float y0f = floorf(uy);
        const float z0f = floorf(uz);
        const float ax = ux - x0f;
        const float ay = uy - y0f;
        const float az = uz - z0f;

        const int x0 = (int)x0f;
        const int y0 = (int)y0f;
        const int z0 = (int)z0f;
        const int x1 = min(x0 + 1, WW - 1);
        const int y1 = min(y0 + 1, HH - 1);
        const int z1 = min(z0 + 1, DD - 1);

        const int zy00 = (z0 * HH + y0) * WW;
        const int zy01 = (z0 * HH + y1) * WW;
        const int zy10 = (z1 * HH + y0) * WW;
        const int zy11 = (z1 * HH + y1) * WW;

        const float c000 = __ldg(src + zy00 + x0);
        const float c001 = __ldg(src + zy00 + x1);
        const float c010 = __ldg(src + zy01 + x0);
        const float c011 = __ldg(src + zy01 + x1);
        const float c100 = __ldg(src + zy10 + x0);
        const float c101 = __ldg(src + zy10 + x1);
        const float c110 = __ldg(src + zy11 + x0);
        const float c111 = __ldg(src + zy11 + x1);

        // 7 lerps
        const float c00 = fmaf(ax, c001 - c000, c000);
        const float c01 = fmaf(ax, c011 - c010, c010);
        const float c10 = fmaf(ax, c101 - c100, c100);
        const float c11 = fmaf(ax, c111 - c110, c110);
        const float c0  = fmaf(ay, c01 - c00, c00);
        const float c1  = fmaf(ay, c11 - c10, c10);
        res[k] = fmaf(az, c1 - c0, c0);
    }

    float4 o = make_float4(res[0], res[1], res[2], res[3]);
    *(float4*)(out + idx) = o;
}

extern "C" void kernel_launch(void* const* d_in, const int* in_sizes, int n_in,
                              void* d_out, int out_size)
{
    const float* src  = (const float*)d_in[0];
    const float* flow = (const float*)d_in[1];
    // d_in[2] (identity grid) intentionally unused — recomputed from indices.
    float* out = (float*)d_out;

    const int threads = 256;
    const int blocks = (NN / 4 + threads - 1) / threads;
    st_warp_kernel<<<blocks, threads>>>(src, flow, out);
}

// round 4
// speedup vs baseline: 1.0168x; 1.0168x over previous
#include <cuda_runtime.h>

// SpatialTransformer: out = trilinear_sample(src, grid+flow) with border clamp.
// src:  [1,1,160,192,160] f32   d_in[0]
// flow: [1,3,160,192,160] f32   d_in[1]  (channel-planar: d,h,w displacement)
// grid: identity meshgrid       d_in[2]  (IGNORED - recomputed from indices)
// out:  [1,1,160,192,160] f32
//
// Math collapse: the reference's normalize -> flip -> unnormalize chain reduces to
//   ux = (w + flow[2]) * W/(W-1) - 0.5   (x -> W axis)
//   uy = (h + flow[1]) * H/(H-1) - 0.5
//   uz = (d + flow[0]) * D/(D-1) - 0.5
// then clamp to [0, S-1], trilinear with clamped +1 neighbor (border padding).

#define DD 160
#define HH 192
#define WW 160
#define NN (DD * HH * WW)

__global__ __launch_bounds__(256) void st_warp_kernel(
    const float* __restrict__ src,
    const float* __restrict__ flow,
    float* __restrict__ out)
{
    const int i4 = blockIdx.x * blockDim.x + threadIdx.x;
    if (i4 >= NN / 4) return;
    const int idx = i4 * 4;

    // decompose linear index (idx..idx+3 share same h,d since W%4==0)
    const int w = idx % WW;
    const int t = idx / WW;
    const int h = t % HH;
    const int d = t / HH;

    // coalesced vector loads of the three flow planes
    const float4 fd = __ldg((const float4*)(flow + idx));            // D-displacement
    const float4 fh = __ldg((const float4*)(flow + NN + idx));       // H-displacement
    const float4 fw = __ldg((const float4*)(flow + 2 * NN + idx));   // W-displacement

    const float sx = (float)WW / (float)(WW - 1);
    const float sy = (float)HH / (float)(HH - 1);
    const float sz = (float)DD / (float)(DD - 1);

    float fwv[4] = {fw.x, fw.y, fw.z, fw.w};
    float fhv[4] = {fh.x, fh.y, fh.z, fh.w};
    float fdv[4] = {fd.x, fd.y, fd.z, fd.w};
    float res[4];

#pragma unroll
    for (int k = 0; k < 4; k++) {
        float ux = ((float)(w + k) + fwv[k]) * sx - 0.5f;
        float uy = ((float)h + fhv[k]) * sy - 0.5f;
        float uz = ((float)d + fdv[k]) * sz - 0.5f;

        ux = fminf(fmaxf(ux, 0.0f), (float)(WW - 1));
        uy = fminf(fmaxf(uy, 0.0f), (float)(HH - 1));
        uz = fminf(fmaxf(uz, 0.0f), (float)(DD - 1));

        const float x0f = floorf(ux);
        const float y0f = floorf(uy);
        const float z0f = floorf(uz);
        const float ax = ux - x0f;
        const float ay = uy - y0f;
        const float az = uz - z0f;

        const int x0 = (int)x0f;
        const int y0 = (int)y0f;
        const int z0 = (int)z0f;
        const int x1 = min(x0 + 1, WW - 1);
        const int y1 = min(y0 + 1, HH - 1);
        const int z1 = min(z0 + 1, DD - 1);

        const int zy00 = (z0 * HH + y0) * WW;
        const int zy01 = (z0 * HH + y1) * WW;
        const int zy10 = (z1 * HH + y0) * WW;
        const int zy11 = (z1 * HH + y1) * WW;

        const float c000 = __ldg(src + zy00 + x0);
        const float c001 = __ldg(src + zy00 + x1);
        const float c010 = __ldg(src + zy01 + x0);
        const float c011 = __ldg(src + zy01 + x1);
        const float c100 = __ldg(src + zy10 + x0);
        const float c101 = __ldg(src + zy10 + x1);
        const float c110 = __ldg(src + zy11 + x0);
        const float c111 = __ldg(src + zy11 + x1);

        // 7 lerps
        const float c00 = fmaf(ax, c001 - c000, c000);
        const float c01 = fmaf(ax, c011 - c010, c010);
        const float c10 = fmaf(ax, c101 - c100, c100);
        const float c11 = fmaf(ax, c111 - c110, c110);
        const float c0  = fmaf(ay, c01 - c00, c00);
        const float c1  = fmaf(ay, c11 - c10, c10);
        res[k] = fmaf(az, c1 - c0, c0);
    }

    float4 o = make_float4(res[0], res[1], res[2], res[3]);
    *(float4*)(out + idx) = o;
}

extern "C" void kernel_launch(void* const* d_in, const int* in_sizes, int n_in,
                              void* d_out, int out_size)
{
    const float* src  = (const float*)d_in[0];
    const float* flow = (const float*)d_in[1];
    // d_in[2] (identity grid) intentionally unused — recomputed from indices.
    float* out = (float*)d_out;

    const int threads = 256;
    const int blocks = (NN / 4 + threads - 1) / threads;
    st_warp_kernel<<<blocks, threads>>>(src, flow, out);
}

// round 5
// speedup vs baseline: 1.0437x; 1.0264x over previous
#include <cuda_runtime.h>

// SpatialTransformer: out = trilinear_sample(src, identity_grid + flow), border clamp.
// src:  [1,1,160,192,160] f32   d_in[0]
// flow: [1,3,160,192,160] f32   d_in[1]  (channel-planar: d,h,w displacement)
// grid: identity meshgrid       d_in[2]  (IGNORED - recomputed from indices)
// out:  [1,1,160,192,160] f32
//
// Math collapse (verified R4, rel_err 2.6e-5):
//   ux = (w + flow[2]) * W/(W-1) - 0.5 ; clamp [0, W-1]; trilinear w/ clamped +1.
//
// Layout choice: 4 voxels per thread batched along Z (stride H*W), so each warp's
// gather LDG spans only 32 consecutive x (~2-3 L1 lines instead of ~5 when
// vectorizing along x). This targets the measured L1tex wavefront bottleneck.

#define DD 160
#define HH 192
#define WW 160
#define PLANE (HH * WW)
#define NN (DD * HH * WW)
#define ZB 4   // z-batch per thread

__global__ __launch_bounds__(256) void st_warp_zb_kernel(
    const float* __restrict__ src,
    const float* __restrict__ flow,
    float* __restrict__ out)
{
    const int tid = blockIdx.x * blockDim.x + threadIdx.x;
    if (tid >= NN / ZB) return;

    // lane-fastest dim = w (32 consecutive x per warp), then h, then z-group
    const int w  = tid % WW;
    const int t  = tid / WW;
    const int h  = t % HH;
    const int dg = t / HH;          // z-group, d = dg*ZB + k
    const int base = (dg * ZB * HH + h) * WW + w;

    const float sx = (float)WW / (float)(WW - 1);
    const float sy = (float)HH / (float)(HH - 1);
    const float sz = (float)DD / (float)(DD - 1);

    // flow loads: 3 channels x ZB z-slices, each warp-coalesced (128B/wavefront)
    float fdv[ZB], fhv[ZB], fwv[ZB];
#pragma unroll
    for (int k = 0; k < ZB; k++) {
        const int idx = base + k * PLANE;
        fdv[k] = __ldg(flow + idx);            // D-displacement
        fhv[k] = __ldg(flow + NN + idx);       // H-displacement
        fwv[k] = __ldg(flow + 2 * NN + idx);   // W-displacement
    }

    float res[ZB];
#pragma unroll
    for (int k = 0; k < ZB; k++) {
        const int d = dg * ZB + k;

        float ux = ((float)w + fwv[k]) * sx - 0.5f;
        float uy = ((float)h + fhv[k]) * sy - 0.5f;
        float uz = ((float)d + fdv[k]) * sz - 0.5f;

        ux = fminf(fmaxf(ux, 0.0f), (float)(WW - 1));
        uy = fminf(fmaxf(uy, 0.0f), (float)(HH - 1));
        uz = fminf(fmaxf(uz, 0.0f), (float)(DD - 1));

        // ux,uy,uz >= 0 -> truncation == floor
        const int x0 = (int)ux;
        const int y0 = (int)uy;
        const int z0 = (int)uz;
        const float ax = ux - (float)x0;
        const float ay = uy - (float)y0;
        const float az = uz - (float)z0;

        const int x1 = min(x0 + 1, WW - 1);
        const int y1 = min(y0 + 1, HH - 1);
        const int z1 = min(z0 + 1, DD - 1);

        const int zy00 = (z0 * HH + y0) * WW;
        const int zy01 = (z0 * HH + y1) * WW;
        const int zy10 = (z1 * HH + y0) * WW;
        const int zy11 = (z1 * HH + y1) * WW;

        const float c000 = __ldg(src + zy00 + x0);
        const float c001 = __ldg(src + zy00 + x1);
        const float c010 = __ldg(src + zy01 + x0);
        const float c011 = __ldg(src + zy01 + x1);
        const float c100 = __ldg(src + zy10 + x0);
        const float c101 = __ldg(src + zy10 + x1);
        const float c110 = __ldg(src + zy11 + x0);
        const float c111 = __ldg(src + zy11 + x1);

        const float c00 = fmaf(ax, c001 - c000, c000);
        const float c01 = fmaf(ax, c011 - c010, c010);
        const float c10 = fmaf(ax, c101 - c100, c100);
        const float c11 = fmaf(ax, c111 - c110, c110);
        const float c0  = fmaf(ay, c01 - c00, c00);
        const float c1  = fmaf(ay, c11 - c10, c10);
        res[k] = fmaf(az, c1 - c0, c0);
    }

#pragma unroll
    for (int k = 0; k < ZB; k++)
        out[base + k * PLANE] = res[k];
}

extern "C" void kernel_launch(void* const* d_in, const int* in_sizes, int n_in,
                              void* d_out, int out_size)
{
    const float* src  = (const float*)d_in[0];
    const float* flow = (const float*)d_in[1];
    // d_in[2] (identity grid) intentionally unused — recomputed from indices.
    float* out = (float*)d_out;

    const int threads = 256;
    const int blocks = (NN / ZB + threads - 1) / threads;
    st_warp_zb_kernel<<<blocks, threads>>>(src, flow, out);
}